// round 1
// baseline (speedup 1.0000x reference)
#include <cuda_runtime.h>

// Problem constants (fixed by the reference).
#define N_IN      262144      // INPUT_LAYER
#define N4        (N_IN / 4)  // 65536 float4 per row
#define HIDDEN    3
#define LAYERS    120
#define NCHAIN    (LAYERS - 1)   // 119
#define OUTPUTS   18

#define BLOCKS    256
#define THREADS   256
// N4 / (BLOCKS*THREADS) == 1 : exactly one float4 per thread per row.

// Scratch (no allocations allowed) — per-block partials + arrival counter.
__device__ float    g_part[BLOCKS * 3];
__device__ unsigned g_count;          // zero-init at load; reset by last block.

__device__ __forceinline__ float tanh_fast(float x) {
    // tanh(x) = 1 - 2/(e^{2x}+1); __expf/__fdividef -> EX2 + RCP approx,
    // rel err ~1e-6 per layer (safe vs 1e-3 over 120 layers).
    float e = __expf(2.0f * x);
    return 1.0f - __fdividef(2.0f, e + 1.0f);
}

__global__ __launch_bounds__(THREADS, 1)
void dqn_fused_kernel(const float* __restrict__ x,
                      const float* __restrict__ W0,     // (3, 262144)
                      const float* __restrict__ bih0,   // (3,)
                      const float* __restrict__ bhh0,   // (3,)
                      const float* __restrict__ Wl,     // (119, 3, 3)
                      const float* __restrict__ bil,    // (119, 3)
                      const float* __restrict__ bhl,    // (119, 3)
                      const float* __restrict__ Wh,     // (18, 120)
                      const float* __restrict__ bh,     // (18,)
                      float* __restrict__ out)          // (3, 18)
{
    const int tid = threadIdx.x;
    const int g   = blockIdx.x * THREADS + tid;

    // ---------------- Phase 1: partial dot products (HBM-bound) -------------
    const float4 xv = reinterpret_cast<const float4*>(x)[g];
    const float4 a0 = reinterpret_cast<const float4*>(W0)[g];
    const float4 a1 = reinterpret_cast<const float4*>(W0 + N_IN)[g];
    const float4 a2 = reinterpret_cast<const float4*>(W0 + 2 * N_IN)[g];

    float s0 = a0.x * xv.x + a0.y * xv.y + a0.z * xv.z + a0.w * xv.w;
    float s1 = a1.x * xv.x + a1.y * xv.y + a1.z * xv.z + a1.w * xv.w;
    float s2 = a2.x * xv.x + a2.y * xv.y + a2.z * xv.z + a2.w * xv.w;

    // Block reduction: warp shuffle, then across the 8 warps via shared.
    #pragma unroll
    for (int off = 16; off > 0; off >>= 1) {
        s0 += __shfl_down_sync(0xFFFFFFFFu, s0, off);
        s1 += __shfl_down_sync(0xFFFFFFFFu, s1, off);
        s2 += __shfl_down_sync(0xFFFFFFFFu, s2, off);
    }

    __shared__ float wsum[3][8];
    const int wid = tid >> 5, lid = tid & 31;
    if (lid == 0) { wsum[0][wid] = s0; wsum[1][wid] = s1; wsum[2][wid] = s2; }
    __syncthreads();

    __shared__ bool is_last;
    if (tid == 0) {
        float b0 = 0.f, b1 = 0.f, b2 = 0.f;
        #pragma unroll
        for (int w = 0; w < 8; ++w) { b0 += wsum[0][w]; b1 += wsum[1][w]; b2 += wsum[2][w]; }
        g_part[blockIdx.x * 3 + 0] = b0;
        g_part[blockIdx.x * 3 + 1] = b1;
        g_part[blockIdx.x * 3 + 2] = b2;
        __threadfence();
        unsigned prev = atomicAdd(&g_count, 1u);
        is_last = (prev == BLOCKS - 1);
    }
    __syncthreads();
    if (!is_last) return;

    // ---------------- Last block: tail --------------------------------------
    __shared__ float sWl[NCHAIN * 9];      // chain weights
    __shared__ float sB [NCHAIN * 3];      // b_ih + b_hh fused
    __shared__ float sWh[OUTPUTS * LAYERS];// head weights
    __shared__ float sH [LAYERS * 3];      // stacked hidden states
    __shared__ float red[3 * BLOCKS];      // partial reduction workspace

    // Cooperative preload (overlaps with the partial reduction below).
    for (int i = tid; i < NCHAIN * 9; i += THREADS) sWl[i] = Wl[i];
    for (int i = tid; i < NCHAIN * 3; i += THREADS) sB[i]  = bil[i] + bhl[i];
    for (int i = tid; i < OUTPUTS * LAYERS; i += THREADS) sWh[i] = Wh[i];

    // Deterministic fixed-order tree reduction of the 256 block partials.
    red[tid]              = g_part[tid * 3 + 0];
    red[BLOCKS + tid]     = g_part[tid * 3 + 1];
    red[2 * BLOCKS + tid] = g_part[tid * 3 + 2];
    __syncthreads();
    #pragma unroll
    for (int k = BLOCKS / 2; k > 0; k >>= 1) {
        if (tid < k) {
            red[tid]              += red[tid + k];
            red[BLOCKS + tid]     += red[BLOCKS + tid + k];
            red[2 * BLOCKS + tid] += red[2 * BLOCKS + tid + k];
        }
        __syncthreads();
    }

    // ---------------- Phase 2: serial 119-layer chain (single thread) -------
    if (tid == 0) {
        float h0 = tanh_fast(red[0]          + bih0[0] + bhh0[0]);
        float h1 = tanh_fast(red[BLOCKS]     + bih0[1] + bhh0[1]);
        float h2 = tanh_fast(red[2 * BLOCKS] + bih0[2] + bhh0[2]);
        sH[0] = h0; sH[1] = h1; sH[2] = h2;

        #pragma unroll 7
        for (int l = 0; l < NCHAIN; ++l) {
            const float* w = &sWl[l * 9];
            const float* b = &sB[l * 3];
            float a0_ = fmaf(w[0], h0, fmaf(w[1], h1, fmaf(w[2], h2, b[0])));
            float a1_ = fmaf(w[3], h0, fmaf(w[4], h1, fmaf(w[5], h2, b[1])));
            float a2_ = fmaf(w[6], h0, fmaf(w[7], h1, fmaf(w[8], h2, b[2])));
            h0 = tanh_fast(a0_);
            h1 = tanh_fast(a1_);
            h2 = tanh_fast(a2_);
            sH[(l + 1) * 3 + 0] = h0;
            sH[(l + 1) * 3 + 1] = h1;
            sH[(l + 1) * 3 + 2] = h2;
        }
        g_count = 0;   // reset for next graph replay
    }
    __syncthreads();

    // ---------------- Phase 3: head (54 parallel dot products) --------------
    if (tid < HIDDEN * OUTPUTS) {
        const int j = tid / OUTPUTS;   // hidden index 0..2
        const int o = tid % OUTPUTS;   // output index 0..17
        float acc = bh[o];
        const float* whrow = &sWh[o * LAYERS];
        #pragma unroll 8
        for (int l = 0; l < LAYERS; ++l)
            acc = fmaf(sH[l * 3 + j], whrow[l], acc);
        out[j * OUTPUTS + o] = acc;    // row-major (3, 18)
    }
}

extern "C" void kernel_launch(void* const* d_in, const int* in_sizes, int n_in,
                              void* d_out, int out_size) {
    const float* x     = (const float*)d_in[0];
    const float* W0    = (const float*)d_in[1];
    const float* bih0  = (const float*)d_in[2];
    const float* bhh0  = (const float*)d_in[3];
    const float* Wl    = (const float*)d_in[4];
    const float* bil   = (const float*)d_in[5];
    const float* bhl   = (const float*)d_in[6];
    const float* Wh    = (const float*)d_in[7];
    const float* bh    = (const float*)d_in[8];
    float* out         = (float*)d_out;

    dqn_fused_kernel<<<BLOCKS, THREADS>>>(x, W0, bih0, bhh0,
                                          Wl, bil, bhl, Wh, bh, out);
}

// round 3
// speedup vs baseline: 1.3081x; 1.3081x over previous
#include <cuda_runtime.h>

// Problem constants (fixed by the reference).
#define N_IN      262144         // INPUT_LAYER
#define HIDDEN    3
#define LAYERS    120
#define NCHAIN    (LAYERS - 1)   // 119
#define OUTPUTS   18

#define BLOCKS    256
#define THREADS   256
// (N_IN/4) / (BLOCKS*THREADS) == 1 : exactly one float4 per thread per W0 row.

#define LOG2E_X2  2.8853900817779268f   // 2/ln(2)

// Scratch (no allocations allowed) — per-block partials + arrival counter.
__device__ float    g_part[BLOCKS * 3];
__device__ unsigned g_count;   // zero at load; reset by block 0 each run.

// tanh from PRE-SCALED argument t = 2x/ln2:
//   e = 2^t = e^{2x};  tanh = 1 - 2/(e+1).
// Saturation-safe: e=inf -> 1-0 = 1; e=0 -> 1-2 = -1. Chain ~40cyc.
__device__ __forceinline__ float tanh_scaled(float t) {
    float e, r;
    asm("ex2.approx.f32 %0, %1;" : "=f"(e) : "f"(t));
    float den = e + 1.0f;
    asm("rcp.approx.f32 %0, %1;" : "=f"(r) : "f"(den));
    return fmaf(-2.0f, r, 1.0f);
}

__global__ __launch_bounds__(THREADS)
void dqn_fused_kernel(const float* __restrict__ x,
                      const float* __restrict__ W0,     // (3, 262144)
                      const float* __restrict__ bih0,   // (3,)
                      const float* __restrict__ bhh0,   // (3,)
                      const float* __restrict__ Wl,     // (119, 3, 3)
                      const float* __restrict__ bil,    // (119, 3)
                      const float* __restrict__ bhl,    // (119, 3)
                      const float* __restrict__ Wh,     // (18, 120)
                      const float* __restrict__ bh,     // (18,)
                      float* __restrict__ out)          // (3, 18)
{
    __shared__ float wsum[3][8];

    const int tid = threadIdx.x;
    const int g   = blockIdx.x * THREADS + tid;

    // ---------------- Phase 1: partial dot products (HBM burst) -------------
    const float4 xv = reinterpret_cast<const float4*>(x)[g];
    const float4 a0 = reinterpret_cast<const float4*>(W0)[g];
    const float4 a1 = reinterpret_cast<const float4*>(W0 + N_IN)[g];
    const float4 a2 = reinterpret_cast<const float4*>(W0 + 2 * N_IN)[g];

    float s0 = a0.x * xv.x + a0.y * xv.y + a0.z * xv.z + a0.w * xv.w;
    float s1 = a1.x * xv.x + a1.y * xv.y + a1.z * xv.z + a1.w * xv.w;
    float s2 = a2.x * xv.x + a2.y * xv.y + a2.z * xv.z + a2.w * xv.w;

    #pragma unroll
    for (int off = 16; off > 0; off >>= 1) {
        s0 += __shfl_down_sync(0xFFFFFFFFu, s0, off);
        s1 += __shfl_down_sync(0xFFFFFFFFu, s1, off);
        s2 += __shfl_down_sync(0xFFFFFFFFu, s2, off);
    }
    const int wid = tid >> 5, lid = tid & 31;
    if (lid == 0) { wsum[0][wid] = s0; wsum[1][wid] = s1; wsum[2][wid] = s2; }
    __syncthreads();

    // ---------------- Non-tail blocks: publish partial and exit -------------
    if (blockIdx.x != 0) {
        if (tid == 0) {
            float b0 = 0.f, b1 = 0.f, b2 = 0.f;
            #pragma unroll
            for (int w = 0; w < 8; ++w) {
                b0 += wsum[0][w]; b1 += wsum[1][w]; b2 += wsum[2][w];
            }
            g_part[blockIdx.x * 3 + 0] = b0;
            g_part[blockIdx.x * 3 + 1] = b1;
            g_part[blockIdx.x * 3 + 2] = b2;
            __threadfence();                 // release partials
            atomicAdd(&g_count, 1u);
        }
        return;
    }

    // ======================= Block 0: tail block =============================
    // Packed chain weights: 12 floats/layer (9 W + 3 fused bias), all
    // PRE-SCALED by 2/ln2 so the per-layer tanh skips its leading FMUL.
    // Padded by one layer so the prefetch of layer l+1 never reads OOB.
    __shared__ float4 sP[(NCHAIN + 1) * 3];
    __shared__ float  sWh[OUTPUTS * LAYERS];
    __shared__ float  sH [LAYERS * 3];
    __shared__ float  red0[BLOCKS], red1[BLOCKS], red2[BLOCKS];
    __shared__ float  s_own[3];

    if (tid == 0) {
        float b0 = 0.f, b1 = 0.f, b2 = 0.f;
        #pragma unroll
        for (int w = 0; w < 8; ++w) {
            b0 += wsum[0][w]; b1 += wsum[1][w]; b2 += wsum[2][w];
        }
        s_own[0] = b0; s_own[1] = b1; s_own[2] = b2;
    }

    // Cooperative preload + repack + pre-scale (overlaps other blocks' phase 1).
    float* sPf = reinterpret_cast<float*>(sP);
    for (int i = tid; i < NCHAIN * 12; i += THREADS) {
        const int l = i / 12, k = i - l * 12;
        const float v = (k < 9) ? Wl[l * 9 + k]
                                : bil[l * 3 + (k - 9)] + bhl[l * 3 + (k - 9)];
        sPf[i] = v * LOG2E_X2;
    }
    for (int i = tid; i < OUTPUTS * LAYERS; i += THREADS) sWh[i] = Wh[i];

    // Wait for all 255 producer blocks (acquire), then reset the counter.
    if (tid == 0) {
        unsigned v;
        do {
            asm volatile("ld.global.acquire.gpu.u32 %0, [%1];"
                         : "=r"(v) : "l"(&g_count));
        } while (v < BLOCKS - 1);
        g_count = 0;                         // ready for next graph replay
    }
    __syncthreads();

    // Gather the 256 partials (own + 255 via L2) and tree-reduce (fixed order
    // -> bitwise deterministic).
    if (tid == 0) {
        red0[0] = s_own[0]; red1[0] = s_own[1]; red2[0] = s_own[2];
    } else {
        red0[tid] = __ldcg(&g_part[tid * 3 + 0]);
        red1[tid] = __ldcg(&g_part[tid * 3 + 1]);
        red2[tid] = __ldcg(&g_part[tid * 3 + 2]);
    }
    __syncthreads();
    #pragma unroll
    for (int k = BLOCKS / 2; k > 0; k >>= 1) {
        if (tid < k) {
            red0[tid] += red0[tid + k];
            red1[tid] += red1[tid + k];
            red2[tid] += red2[tid + k];
        }
        __syncthreads();
    }

    // ---------------- Phase 2: serial 119-layer chain (1 thread) ------------
    if (tid == 0) {
        float h0 = tanh_scaled((red0[0] + bih0[0] + bhh0[0]) * LOG2E_X2);
        float h1 = tanh_scaled((red1[0] + bih0[1] + bhh0[1]) * LOG2E_X2);
        float h2 = tanh_scaled((red2[0] + bih0[2] + bhh0[2]) * LOG2E_X2);
        sH[0] = h0; sH[1] = h1; sH[2] = h2;

        // Software-pipelined: fetch layer l+1 (3x LDS.128) while layer l's
        // tanh chain is in flight.
        float4 c0 = sP[0], c1 = sP[1], c2 = sP[2];
        #pragma unroll 7
        for (int l = 0; l < NCHAIN; ++l) {
            const float4 n0 = sP[(l + 1) * 3 + 0];
            const float4 n1 = sP[(l + 1) * 3 + 1];
            const float4 n2 = sP[(l + 1) * 3 + 2];
            // layout: w = {c0.x..c0.w, c1.x..c1.w, c2.x}, b = {c2.y, c2.z, c2.w}
            // (all pre-scaled by 2/ln2)
            const float t0 = fmaf(c0.x, h0, fmaf(c0.y, h1, fmaf(c0.z, h2, c2.y)));
            const float t1 = fmaf(c0.w, h0, fmaf(c1.x, h1, fmaf(c1.y, h2, c2.z)));
            const float t2 = fmaf(c1.z, h0, fmaf(c1.w, h1, fmaf(c2.x, h2, c2.w)));
            h0 = tanh_scaled(t0);
            h1 = tanh_scaled(t1);
            h2 = tanh_scaled(t2);
            sH[(l + 1) * 3 + 0] = h0;
            sH[(l + 1) * 3 + 1] = h1;
            sH[(l + 1) * 3 + 2] = h2;
            c0 = n0; c1 = n1; c2 = n2;
        }
    }
    __syncthreads();

    // ---------------- Phase 3: head (54 parallel dot products) --------------
    if (tid < HIDDEN * OUTPUTS) {
        const int j = tid / OUTPUTS;     // hidden index 0..2
        const int o = tid % OUTPUTS;     // output index 0..17
        float acc = bh[o];
        const float* whrow = &sWh[o * LAYERS];
        #pragma unroll 8
        for (int l = 0; l < LAYERS; ++l)
            acc = fmaf(sH[l * 3 + j], whrow[l], acc);
        out[j * OUTPUTS + o] = acc;      // row-major (3, 18)
    }
}

extern "C" void kernel_launch(void* const* d_in, const int* in_sizes, int n_in,
                              void* d_out, int out_size) {
    const float* x    = (const float*)d_in[0];
    const float* W0   = (const float*)d_in[1];
    const float* bih0 = (const float*)d_in[2];
    const float* bhh0 = (const float*)d_in[3];
    const float* Wl   = (const float*)d_in[4];
    const float* bil  = (const float*)d_in[5];
    const float* bhl  = (const float*)d_in[6];
    const float* Wh   = (const float*)d_in[7];
    const float* bh   = (const float*)d_in[8];
    float* out        = (float*)d_out;

    dqn_fused_kernel<<<BLOCKS, THREADS>>>(x, W0, bih0, bhh0,
                                          Wl, bil, bhl, Wh, bh, out);
}